// round 14
// baseline (speedup 1.0000x reference)
#include <cuda_runtime.h>

// GCBFSafetyLayer — FINAL (frozen; measured-best configuration, unchanged).
//
// Algebraic reduction (verified rel_err = 0.0, 14/14 rounds):
//   L_g_h = dh_dx @ g == 0 identically. dh_dx = [jac_pos | 0] puts the
//   position Jacobian in state columns 0..1; g = [0 ; I/MASS] has nonzero
//   rows only at 2..3 — disjoint supports, the product vanishes. In
//   project(), every constraint row a = 0, so an = ||a||^2 = 0 fails the
//   (an > 1e-6) gate on every inner iteration of every outer iteration ->
//   u is never modified -> safe_action == raw_action BIT-EXACT.
// Remaining work: copy d_in[3] (B*N*P = 65536 f32 = 16384 float4) to d_out.
//
// Fourteen-round measurement summary:
//   This exact source — ncu: 4.13-4.61 us (9 samples, sigma ~0.15)
//                       harness: 4.58-5.89 us (8 samples, sigma ~0.55)
//   ncu and harness samples are uncorrelated (R12: best ncu 4.32 with worst
//   harness 5.89) — harness timing is host-side replay jitter, not kernel.
//   CE memcpyAsync node: 4.61, 5.89 us (statistically tied, no ncu view)
//   Rejected: 64x256 bounds-checked (6.43), 2 ld/thread @64 CTAs (4.93),
//             __stcs streaming stores (5.41 — .cs evict costs on the
//             harness's d_out re-read).
// Duration = launch/graph-replay floor (T_ovh ~5000 cyc + one DRAM round
// trip). The copy itself is ~64ns of DRAM time (256KB at 0.8% utilization)
// inside a ~4.3us launch envelope — no .cu-level change can move it. Final.

__global__ __launch_bounds__(128, 1)
void gcbf_copy_kernel(const float4* __restrict__ src, float4* __restrict__ dst) {
    int i = blockIdx.x * 128 + threadIdx.x;
    dst[i] = src[i];
}

extern "C" void kernel_launch(void* const* d_in, const int* in_sizes, int n_in,
                              void* d_out, int out_size) {
    // inputs: [0] positions, [1] velocities, [2] obstacles, [3] raw_action
    gcbf_copy_kernel<<<128, 128>>>((const float4*)d_in[3], (float4*)d_out);
}

// round 15
// speedup vs baseline: 1.2708x; 1.2708x over previous
#include <cuda_runtime.h>

// GCBFSafetyLayer — FINAL (frozen; measured-best configuration, unchanged).
//
// Algebraic reduction (verified rel_err = 0.0, 15/15 rounds):
//   L_g_h = dh_dx @ g == 0 identically. dh_dx = [jac_pos | 0] puts the
//   position Jacobian in state columns 0..1; g = [0 ; I/MASS] has nonzero
//   rows only at 2..3 — disjoint supports, the product vanishes. In
//   project(), every constraint row a = 0, so an = ||a||^2 = 0 fails the
//   (an > 1e-6) gate on every inner iteration of every outer iteration ->
//   u is never modified -> safe_action == raw_action BIT-EXACT.
// Remaining work: copy d_in[3] (B*N*P = 65536 f32 = 16384 float4) to d_out.
//
// Fifteen-round measurement summary:
//   This exact source — ncu: 4.13-4.64 us (10 samples, sigma ~0.15)
//                       harness: 4.58-5.89 us (9 samples, sigma ~0.55)
//   ncu and harness samples are uncorrelated (R12: best ncu 4.32 with worst
//   harness 5.89) — harness timing is host-side replay jitter, not kernel.
//   CE memcpyAsync node: 4.61, 5.89 us (statistically tied, no ncu view)
//   Rejected: 64x256 bounds-checked (6.43), 2 ld/thread @64 CTAs (4.93),
//             __stcs streaming stores (5.41 — .cs evict costs on the
//             harness's d_out re-read).
// Duration = launch/graph-replay floor (T_ovh ~5000 cyc + one DRAM round
// trip). The copy itself is ~64ns of DRAM time (256KB at <1% utilization)
// inside a ~4.4us launch envelope — no .cu-level change can move it. Every
// applicable strategy-catalog lever has been probed and measured in-band or
// worse; any further variant could only "win" by sampling noise. Final.

__global__ __launch_bounds__(128, 1)
void gcbf_copy_kernel(const float4* __restrict__ src, float4* __restrict__ dst) {
    int i = blockIdx.x * 128 + threadIdx.x;
    dst[i] = src[i];
}

extern "C" void kernel_launch(void* const* d_in, const int* in_sizes, int n_in,
                              void* d_out, int out_size) {
    // inputs: [0] positions, [1] velocities, [2] obstacles, [3] raw_action
    gcbf_copy_kernel<<<128, 128>>>((const float4*)d_in[3], (float4*)d_out);
}